// round 5
// baseline (speedup 1.0000x reference)
#include <cuda_runtime.h>
#include <cuda_fp16.h>
#include <cstdint>

#define DI __device__ __forceinline__

// ---------------------------------------------------------------------------
// Problem constants
// ---------------------------------------------------------------------------
#define BATCH_  8192L
#define WTOT_   41943040L      // 4096*1024 + 4096*4096*2 + 1024*4096
#define HBUF_   33554432L      // 8192*4096

// GEMM tiling
#define BM 256
#define BN 128
#define BK 32                      // halves per K-chunk
#define STAGES 4
#define A_BYTES (BM * 128)         // 32768  (128B row = 64B hi | 64B lo)
#define B_BYTES (BN * 128)         // 16384
#define STAGE_BYTES (A_BYTES + B_BYTES)      // 49152
#define SMEM_BYTES (STAGES * STAGE_BYTES)    // 196608

// ---------------------------------------------------------------------------
// Scratch: __device__ globals (no runtime allocation anywhere)
// ---------------------------------------------------------------------------
__device__ __half g_Whi[WTOT_];
__device__ __half g_Wlo[WTOT_];
__device__ float  g_bias[4 * 4096];
__device__ __half g_hAhi[HBUF_], g_hAlo[HBUF_];
__device__ __half g_hBhi[HBUF_], g_hBlo[HBUF_];

// ---------------------------------------------------------------------------
// Small helpers
// ---------------------------------------------------------------------------
DI uint32_t smem_u32(const void* p) {
    uint32_t a;
    asm("{ .reg .u64 t; cvta.to.shared.u64 t, %1; cvt.u32.u64 %0, t; }"
        : "=r"(a) : "l"(p));
    return a;
}

DI void cp16(uint32_t dst, const void* src) {
    asm volatile("cp.async.cg.shared.global [%0], [%1], 16;"
                 :: "r"(dst), "l"(src));
}

DI void ldsm_x4(uint32_t* r, uint32_t addr) {
    asm volatile("ldmatrix.sync.aligned.m8n8.x4.shared.b16 {%0,%1,%2,%3}, [%4];"
                 : "=r"(r[0]), "=r"(r[1]), "=r"(r[2]), "=r"(r[3]) : "r"(addr));
}

DI void ldsm_x2(uint32_t* r, uint32_t addr) {
    asm volatile("ldmatrix.sync.aligned.m8n8.x2.shared.b16 {%0,%1}, [%2];"
                 : "=r"(r[0]), "=r"(r[1]) : "r"(addr));
}

DI void mma16816(float* d, const uint32_t* a, const uint32_t* b) {
    asm volatile(
        "mma.sync.aligned.m16n8k16.row.col.f32.f16.f16.f32 "
        "{%0,%1,%2,%3}, {%4,%5,%6,%7}, {%8,%9}, {%0,%1,%2,%3};"
        : "+f"(d[0]), "+f"(d[1]), "+f"(d[2]), "+f"(d[3])
        : "r"(a[0]), "r"(a[1]), "r"(a[2]), "r"(a[3]), "r"(b[0]), "r"(b[1]));
}

DI float softplus_f(float s) {
    return (s > 20.0f) ? s : log1pf(expf(s));
}

DI void split2(float v, __half& hi, __half& lo) {
    hi = __float2half_rn(v);
    lo = __float2half_rn(v - __half2float(hi));
}

// ---------------------------------------------------------------------------
// Prep kernels
// ---------------------------------------------------------------------------
__global__ void prep_w(const float* __restrict__ mw, const float* __restrict__ sw,
                       const float* __restrict__ zw, long woff, long n)
{
    long t = (long)blockIdx.x * blockDim.x + threadIdx.x;
    long stride = (long)gridDim.x * blockDim.x;
    for (long e = t * 4; e < n; e += stride * 4) {
        float4 m = *(const float4*)(mw + e);
        float4 s = *(const float4*)(sw + e);
        float4 z = *(const float4*)(zw + e);
        float a0 = m.x + softplus_f(s.x) * z.x;
        float a1 = m.y + softplus_f(s.y) * z.y;
        float a2 = m.z + softplus_f(s.z) * z.z;
        float a3 = m.w + softplus_f(s.w) * z.w;
        __half h0, h1, h2, h3, l0, l1, l2, l3;
        split2(a0, h0, l0); split2(a1, h1, l1);
        split2(a2, h2, l2); split2(a3, h3, l3);
        __half2* ph = (__half2*)(g_Whi + woff + e);
        __half2* pl = (__half2*)(g_Wlo + woff + e);
        ph[0] = __halves2half2(h0, h1); ph[1] = __halves2half2(h2, h3);
        pl[0] = __halves2half2(l0, l1); pl[1] = __halves2half2(l2, l3);
    }
}

__global__ void prep_b(const float* __restrict__ mb, const float* __restrict__ sb,
                       const float* __restrict__ zb, int layer, int n)
{
    int i = blockIdx.x * blockDim.x + threadIdx.x;
    if (i < n)
        g_bias[layer * 4096 + i] = mb[i] + softplus_f(sb[i]) * zb[i];
}

__global__ void prep_x(const float* __restrict__ x, long n)
{
    long t = (long)blockIdx.x * blockDim.x + threadIdx.x;
    long stride = (long)gridDim.x * blockDim.x;
    for (long e = t * 4; e < n; e += stride * 4) {
        float4 v = *(const float4*)(x + e);
        __half h0, h1, h2, h3, l0, l1, l2, l3;
        split2(v.x, h0, l0); split2(v.y, h1, l1);
        split2(v.z, h2, l2); split2(v.w, h3, l3);
        __half2* ph = (__half2*)(g_hAhi + e);
        __half2* pl = (__half2*)(g_hAlo + e);
        ph[0] = __halves2half2(h0, h1); ph[1] = __halves2half2(h2, h3);
        pl[0] = __halves2half2(l0, l1); pl[1] = __halves2half2(l2, l3);
    }
}

// ---------------------------------------------------------------------------
// Stage loader: one BK=32 chunk of A(256 rows) + B(128 rows), hi|lo planes.
// Row layout in SMEM: 128B = [hi k0..31 (64B) | lo k0..31 (64B)], SW128 swizzle
// phys16B granule = (col ^ (row&7)); writes conflict-free per lane-octet.
// ---------------------------------------------------------------------------
DI void load_stage(uint32_t stageBase, int K, long kc,
                   const __half* aHi, const __half* aLo,
                   const __half* bHi, const __half* bLo,
                   uint32_t aDst0, uint32_t bDst0)
{
    const long rstride = 64L * K;   // 64 rows forward, in halves
#pragma unroll
    for (int i2 = 0; i2 < 4; ++i2) {
        long so = kc + (long)i2 * rstride;
        uint32_t d = stageBase + aDst0 + (uint32_t)i2 * 8192u;
        cp16(d,      aHi + so);
        cp16(d ^ 64, aLo + so);
        if (i2 < 2) {
            uint32_t db = stageBase + (uint32_t)A_BYTES + bDst0 + (uint32_t)i2 * 8192u;
            cp16(db,      bHi + so);
            cp16(db ^ 64, bLo + so);
        }
    }
    asm volatile("cp.async.commit_group;" ::: "memory");
}

// ---------------------------------------------------------------------------
// Split-fp16 GEMM:  O[BM,BN] tile of  H[B,K] @ W[dout,K]^T + bias (+tanh)
// acc = Hhi*Whi + Hhi*Wlo + Hlo*Whi  (fp32 register accumulators)
// 8 warps as 4(m) x 2(n); warp tile 64x64; mma.sync m16n8k16
// ---------------------------------------------------------------------------
__global__ void __launch_bounds__(256, 1)
gemm_split(int inSel, long woff, int K, int dout, int bOff, int last,
           float* __restrict__ out)
{
    extern __shared__ __align__(128) uint8_t smem_raw[];
    const uint32_t sb = smem_u32(smem_raw);
    const int tid  = threadIdx.x;
    const int lane = tid & 31;
    const int wid  = tid >> 5;
    const int wm   = wid >> 1;      // 0..3
    const int wn   = wid & 1;       // 0..1

    const __half* Hhi = inSel ? g_hBhi : g_hAhi;
    const __half* Hlo = inSel ? g_hBlo : g_hAlo;
    __half* Ohi = inSel ? g_hAhi : g_hBhi;
    __half* Olo = inSel ? g_hAlo : g_hBlo;
    const __half* Whi = g_Whi + woff;
    const __half* Wlo = g_Wlo + woff;

    const long rowW = (long)blockIdx.x * BN;   // output-col base (x fastest: L2 reuse)
    const long rowH = (long)blockIdx.y * BM;   // batch-row base

    // ---- loader thread mapping (conflict-free smem writes) ----
    const int  lrow  = (tid & 7) + 8 * ((tid >> 5) & 7);  // 0..63
    const int  c4    = (tid >> 3) & 3;                    // 16B granule 0..3 (hi plane)
    const uint32_t swzb = (uint32_t)((lrow & 7) << 4);
    const uint32_t aDst0 = (uint32_t)lrow * 128u + (((uint32_t)c4 * 16u) ^ swzb);
    const uint32_t bDst0 = aDst0;   // same row/col pattern, B rows 0..127
    const __half* aSrcHi = Hhi + (rowH + lrow) * (long)K + c4 * 8;
    const __half* aSrcLo = Hlo + (rowH + lrow) * (long)K + c4 * 8;
    const __half* bSrcHi = Whi + (rowW + lrow) * (long)K + c4 * 8;
    const __half* bSrcLo = Wlo + (rowW + lrow) * (long)K + c4 * 8;

    // ---- ldmatrix per-lane address bases (offset within stage; p=0, kk=0) ----
    uint32_t aAddr[4];
#pragma unroll
    for (int mf = 0; mf < 4; ++mf) {
        uint32_t r = (uint32_t)(wm * 64 + mf * 16 + (lane & 15));
        uint32_t c = (uint32_t)((lane >> 4) << 4);
        aAddr[mf] = r * 128u + (c ^ ((r & 7u) << 4));
    }
    uint32_t bAddr[8];
#pragma unroll
    for (int nf = 0; nf < 8; ++nf) {
        uint32_t r = (uint32_t)(wn * 64 + nf * 8 + (lane & 7));
        uint32_t c = (uint32_t)(((lane >> 3) & 1) << 4);
        bAddr[nf] = (uint32_t)A_BYTES + r * 128u + (c ^ ((r & 7u) << 4));
    }

    float acc[4][8][4];
#pragma unroll
    for (int mf = 0; mf < 4; ++mf)
#pragma unroll
        for (int nf = 0; nf < 8; ++nf)
#pragma unroll
            for (int q = 0; q < 4; ++q) acc[mf][nf][q] = 0.0f;

    const int nIter = K / BK;

    // prologue: 3 stages in flight
    load_stage(sb + 0u * STAGE_BYTES, K, 0L * BK, aSrcHi, aSrcLo, bSrcHi, bSrcLo, aDst0, bDst0);
    load_stage(sb + 1u * STAGE_BYTES, K, 1L * BK, aSrcHi, aSrcLo, bSrcHi, bSrcLo, aDst0, bDst0);
    load_stage(sb + 2u * STAGE_BYTES, K, 2L * BK, aSrcHi, aSrcLo, bSrcHi, bSrcLo, aDst0, bDst0);

    for (int it = 0; it < nIter; ++it) {
        asm volatile("cp.async.wait_group 2;" ::: "memory");
        __syncthreads();

        if (it + 3 < nIter)
            load_stage(sb + (uint32_t)((it + 3) & 3) * STAGE_BYTES, K, (long)(it + 3) * BK,
                       aSrcHi, aSrcLo, bSrcHi, bSrcLo, aDst0, bDst0);
        else
            asm volatile("cp.async.commit_group;" ::: "memory");

        const uint32_t stg = sb + (uint32_t)(it & 3) * STAGE_BYTES;

#pragma unroll
        for (int kk = 0; kk < 2; ++kk) {
            const uint32_t kx = (uint32_t)kk * 32u;
            uint32_t ah[4][4], al[4][4];
#pragma unroll
            for (int mf = 0; mf < 4; ++mf) {
                ldsm_x4(ah[mf], stg + (aAddr[mf] ^ kx));
                ldsm_x4(al[mf], stg + (aAddr[mf] ^ kx ^ 64u));
            }
#pragma unroll
            for (int nf = 0; nf < 8; ++nf) {
                uint32_t bh[2], bl[2];
                ldsm_x2(bh, stg + (bAddr[nf] ^ kx));
                ldsm_x2(bl, stg + (bAddr[nf] ^ kx ^ 64u));
#pragma unroll
                for (int mf = 0; mf < 4; ++mf) {
                    mma16816(acc[mf][nf], ah[mf], bh);
                    mma16816(acc[mf][nf], ah[mf], bl);
                    mma16816(acc[mf][nf], al[mf], bh);
                }
            }
        }
    }

    asm volatile("cp.async.wait_group 0;" ::: "memory");

    // ---- epilogue ----
    const int r0 = lane >> 2;
    const int c0 = (lane & 3) * 2;
#pragma unroll
    for (int mf = 0; mf < 4; ++mf) {
#pragma unroll
        for (int nf = 0; nf < 8; ++nf) {
            const long col = rowW + wn * 64 + nf * 8 + c0;
            const float2 bv = *(const float2*)(g_bias + bOff + col);
#pragma unroll
            for (int h = 0; h < 2; ++h) {
                const long m = rowH + wm * 64 + mf * 16 + r0 + h * 8;
                float v0 = acc[mf][nf][h * 2 + 0] + bv.x;
                float v1 = acc[mf][nf][h * 2 + 1] + bv.y;
                if (last) {
                    *(float2*)(out + m * dout + col) = make_float2(v0, v1);
                } else {
                    v0 = tanhf(v0); v1 = tanhf(v1);
                    __half h0, l0, h1, l1;
                    split2(v0, h0, l0); split2(v1, h1, l1);
                    *(__half2*)(Ohi + m * dout + col) = __halves2half2(h0, h1);
                    *(__half2*)(Olo + m * dout + col) = __halves2half2(l0, l1);
                }
            }
        }
    }
}

// ---------------------------------------------------------------------------
// Host launcher
// ---------------------------------------------------------------------------
extern "C" void kernel_launch(void* const* d_in, const int* in_sizes, int n_in,
                              void* d_out, int out_size)
{
    (void)in_sizes; (void)n_in; (void)out_size;

    static const int  DIN[4]   = {1024, 4096, 4096, 4096};
    static const int  DOUTL[4] = {4096, 4096, 4096, 1024};
    static const long WOFF[4]  = {0L, 4194304L, 20971520L, 37748736L};

    cudaFuncSetAttribute(gemm_split, cudaFuncAttributeMaxDynamicSharedMemorySize,
                         SMEM_BYTES);

    const float* x = (const float*)d_in[0];
    prep_x<<<512, 256>>>(x, BATCH_ * 1024L);

    for (int j = 0; j < 4; ++j) {
        const float* mw = (const float*)d_in[1 + 6 * j];
        const float* sw = (const float*)d_in[2 + 6 * j];
        const float* zw = (const float*)d_in[3 + 6 * j];
        const float* mb = (const float*)d_in[4 + 6 * j];
        const float* sb = (const float*)d_in[5 + 6 * j];
        const float* zb = (const float*)d_in[6 + 6 * j];
        long n = (long)DOUTL[j] * DIN[j];
        prep_w<<<2048, 256>>>(mw, sw, zw, WOFF[j], n);
        prep_b<<<16, 256>>>(mb, sb, zb, j, DOUTL[j]);
    }

    for (int j = 0; j < 4; ++j) {
        dim3 grid(DOUTL[j] / BN, (int)(BATCH_ / BM));
        gemm_split<<<grid, 256, SMEM_BYTES>>>(j & 1, WOFF[j], DIN[j], DOUTL[j],
                                              j * 4096, (j == 3) ? 1 : 0,
                                              (float*)d_out);
    }
}